// round 1
// baseline (speedup 1.0000x reference)
#include <cuda_runtime.h>
#include <cuda_bf16.h>

// Problem constants
#define B_   8
#define NUM_ 128
#define L_   (NUM_ * NUM_)      // 16384
#define C_   512
#define H_   8
#define DK_  64
#define TOPK_ 4

// Scratch (allocation-free rule: __device__ globals)
__device__ float    g_attn[B_ * L_ * H_];   // (B, num, num, H) layout, 4 MiB
__device__ unsigned g_mask[NUM_];           // column mask over j

// ---------------------------------------------------------------------------
// Kernel 0: zero the column mask (must happen every replay)
// ---------------------------------------------------------------------------
__global__ void zero_mask_kernel() {
    if (threadIdx.x < NUM_) g_mask[threadIdx.x] = 0u;
}

// ---------------------------------------------------------------------------
// Kernel 1: cosine similarity per (b, l, h), relu, write attn.
// One warp per (b,l). Each iteration: 32 lanes load 128 contiguous floats
// (one float4 each) covering heads 2*iter and 2*iter+1; segmented 16-lane
// shuffle reduction produces both head results.
// ---------------------------------------------------------------------------
__global__ __launch_bounds__(256) void cosine_kernel(
    const float4* __restrict__ q4, const float4* __restrict__ k4)
{
    const int warpId = (blockIdx.x * blockDim.x + threadIdx.x) >> 5;  // (b*L + l)
    const int lane   = threadIdx.x & 31;
    const long base4 = (long)warpId * (C_ / 4);   // 128 float4 per vector

    #pragma unroll
    for (int iter = 0; iter < 4; ++iter) {
        float4 qv = q4[base4 + iter * 32 + lane];
        float4 kv = k4[base4 + iter * 32 + lane];

        float dot = qv.x * kv.x + qv.y * kv.y + qv.z * kv.z + qv.w * kv.w;
        float qq  = qv.x * qv.x + qv.y * qv.y + qv.z * qv.z + qv.w * qv.w;
        float kk  = kv.x * kv.x + kv.y * kv.y + kv.z * kv.z + kv.w * kv.w;

        // reduce within each 16-lane half (one head per half)
        #pragma unroll
        for (int off = 8; off > 0; off >>= 1) {
            dot += __shfl_xor_sync(0xffffffffu, dot, off);
            qq  += __shfl_xor_sync(0xffffffffu, qq,  off);
            kk  += __shfl_xor_sync(0xffffffffu, kk,  off);
        }

        if ((lane & 15) == 0) {
            const int h = iter * 2 + (lane >> 4);
            const float denom = fmaxf(sqrtf(qq) * sqrtf(kk), 1e-8f);
            const float p = fmaxf(dot / denom, 0.0f);
            g_attn[(long)warpId * H_ + h] = p;
        }
    }
}

// ---------------------------------------------------------------------------
// Kernel 2: per-(b,i,h) top-4 over j, union into g_mask.
// One warp per row (8192 rows). Tie-break: smaller j wins (matches lax.top_k).
// ---------------------------------------------------------------------------
__global__ __launch_bounds__(256) void topk_kernel()
{
    const int warpId = (blockIdx.x * blockDim.x + threadIdx.x) >> 5;
    const int lane   = threadIdx.x & 31;
    if (warpId >= B_ * NUM_ * H_) return;

    const int h  = warpId & (H_ - 1);
    const int bi = warpId >> 3;                  // b*num + i
    const float* row = g_attn + (long)bi * NUM_ * H_ + h;

    float v[4];
    int   jj[4];
    #pragma unroll
    for (int t = 0; t < 4; ++t) {
        const int j = lane + 32 * t;
        v[t]  = row[(long)j * H_];
        jj[t] = j;
    }

    #pragma unroll
    for (int r = 0; r < TOPK_; ++r) {
        // local best (max value, smaller index on ties)
        float bv = v[0]; int bj = jj[0];
        #pragma unroll
        for (int t = 1; t < 4; ++t)
            if (v[t] > bv || (v[t] == bv && jj[t] < bj)) { bv = v[t]; bj = jj[t]; }

        // warp argmax
        #pragma unroll
        for (int off = 16; off > 0; off >>= 1) {
            const float ov = __shfl_xor_sync(0xffffffffu, bv, off);
            const int   oj = __shfl_xor_sync(0xffffffffu, bj, off);
            if (ov > bv || (ov == bv && oj < bj)) { bv = ov; bj = oj; }
        }

        if (lane == 0) g_mask[bj] = 1u;          // races benign: all write 1

        #pragma unroll
        for (int t = 0; t < 4; ++t)
            if (jj[t] == bj) v[t] = -1e30f;      // remove winner
    }
}

// ---------------------------------------------------------------------------
// Kernel 3: out[b,i,j,h] = attn * roi[b,i,j] * mask[j]
// ---------------------------------------------------------------------------
__global__ __launch_bounds__(256) void out_kernel(
    const float* __restrict__ roi, float* __restrict__ out)
{
    const int idx = blockIdx.x * blockDim.x + threadIdx.x;  // 1,048,576
    const int j   = (idx >> 3) & (NUM_ - 1);
    const int bij = idx >> 3;
    const float m = g_mask[j] ? 1.0f : 0.0f;
    out[idx] = g_attn[idx] * __ldg(&roi[bij]) * m;
}

// ---------------------------------------------------------------------------
extern "C" void kernel_launch(void* const* d_in, const int* in_sizes, int n_in,
                              void* d_out, int out_size)
{
    const float4* q4  = (const float4*)d_in[0];
    const float4* k4  = (const float4*)d_in[1];
    const float*  roi = (const float*)d_in[2];
    float*        out = (float*)d_out;

    zero_mask_kernel<<<1, 128>>>();

    // B*L warps, 8 warps per 256-thread block
    const int cos_blocks = (B_ * L_) / 8;                   // 16384
    cosine_kernel<<<cos_blocks, 256>>>(q4, k4);

    const int rows = B_ * NUM_ * H_;                        // 8192 warps
    topk_kernel<<<(rows * 32) / 256, 256>>>();              // 1024 blocks

    const int total = B_ * NUM_ * NUM_ * H_;                // 1,048,576
    out_kernel<<<total / 256, 256>>>(roi, out);
}